// round 16
// baseline (speedup 1.0000x reference)
#include <cuda_runtime.h>
#include <cuda_bf16.h>
#include <cstdint>
#include <math_constants.h>

#define BB 8
#define CC 256
#define NN 4096

// ---------------- device scratch (allocation-free rule) ----------------
__device__ __nv_bfloat16 g_Ft_hi[BB * NN * CC];   // feat^T [b][n][c]
__device__ __nv_bfloat16 g_Ft_lo[BB * NN * CC];
__device__ __nv_bfloat16 g_Zt_hi[BB * NN * CC];   // Z^T [b][m][c]
__device__ __nv_bfloat16 g_Zt_lo[BB * NN * CC];
__device__ __nv_bfloat16 g_Gk_hi[CC * CC];        // G [c][e]
__device__ __nv_bfloat16 g_Gk_lo[CC * CC];

// ---------------- SMEM layout: k_z_mma (unchanged, 128-row tiles) ----------
#define CH       16384                 // 128x64 bf16 chunk, SW128
#define OFF_A    0                     // 8 chunks = 131072
#define OFF_B    131072                // 2 bufs x (hi+lo) = 65536
#define BUFSZ    32768
#define SMEM_Z   199680

// ---------------- SMEM layout: k_attn_mma (64-row tiles, 2 CTA/SM) ---------
#define ACH      8192                  // A chunk: 64 rows x 128B (SW128)
#define AT_A     0                     // 8 chunks (hi 0-3, lo 4-7) = 65536
#define AT_B     65536                 // 2 stages x (hi 8KB + lo 8KB) = 32768
#define BSTG     16384
#define AT_EPI   98304
#define AE_DLOG  (AT_EPI + 0)          // 64 floats
#define AE_MM    (AT_EPI + 256)        // [2][64]
#define AE_LL    (AT_EPI + 768)        // [2][64]
#define AE_DIAG  (AT_EPI + 1280)       // 64 floats
#define SMEM_AT  99840

__device__ __forceinline__ uint32_t smem_u32(const void* p) {
    uint32_t a;
    asm("{ .reg .u64 t; cvta.to.shared.u64 t, %1; cvt.u32.u64 %0, t; }" : "=r"(a) : "l"(p));
    return a;
}

#define CPA_COMMIT() asm volatile("cp.async.commit_group;" ::: "memory")
#define CPA_WAIT0()  asm volatile("cp.async.wait_group 0;" ::: "memory")

// ---- 128x64 chunk (SW128, 128B rows), 256 threads ----
__device__ __forceinline__ void cpa_chunk(uint32_t dst, const __nv_bfloat16* g, int tid) {
#pragma unroll
    for (int it = 0; it < 4; it++) {
        int u = tid + it * 256;
        int row = u >> 3, seg = u & 7;
        uint32_t bo = (uint32_t)(row * 128 + seg * 16);
        bo ^= ((bo >> 3) & 0x70);
        asm volatile("cp.async.cg.shared.global [%0], [%1], 16;"
                     :: "r"(dst + bo), "l"((const void*)(g + row * CC + seg * 8)) : "memory");
    }
}
__device__ __forceinline__ void copy_chunk(char* sm, uint32_t dst, const __nv_bfloat16* g, int tid) {
#pragma unroll
    for (int it = 0; it < 4; it++) {
        int u = tid + it * 256;
        int row = u >> 3, seg = u & 7;
        uint4 v = *(const uint4*)(g + row * CC + seg * 8);
        uint32_t bo = (uint32_t)(row * 128 + seg * 16);
        bo ^= ((bo >> 3) & 0x70);
        *(uint4*)(sm + dst + bo) = v;
    }
}

// ---- A chunk for attn: 64 rows x 64 cols (SW128, 128B rows), 256 threads ----
__device__ __forceinline__ void copy_chunkA64(char* sm, uint32_t dst, const __nv_bfloat16* g, int tid) {
#pragma unroll
    for (int it = 0; it < 2; it++) {
        int u = tid + it * 256;
        int row = u >> 3, seg = u & 7;
        uint4 v = *(const uint4*)(g + row * CC + seg * 8);
        uint32_t bo = (uint32_t)(row * 128 + seg * 16);
        bo ^= ((bo >> 3) & 0x70);
        *(uint4*)(sm + dst + bo) = v;
    }
}

// ---- B chunk for attn: 128 rows x 32 cols (SW64, 64B rows), 256 threads ----
__device__ __forceinline__ void cpa_chunk32(uint32_t dst, const __nv_bfloat16* g, int tid) {
#pragma unroll
    for (int it = 0; it < 2; it++) {
        int u = tid + it * 256;
        int row = u >> 2, seg = u & 3;
        uint32_t bo = (uint32_t)(row * 64 + seg * 16);
        bo ^= ((bo >> 3) & 0x30);
        asm volatile("cp.async.cg.shared.global [%0], [%1], 16;"
                     :: "r"(dst + bo), "l"((const void*)(g + row * CC + seg * 8)) : "memory");
    }
}

__device__ __forceinline__ void ldsm4(uint32_t addr, uint32_t r[4]) {
    asm volatile("ldmatrix.sync.aligned.m8n8.x4.shared.b16 {%0,%1,%2,%3}, [%4];"
                 : "=r"(r[0]), "=r"(r[1]), "=r"(r[2]), "=r"(r[3]) : "r"(addr));
}

__device__ __forceinline__ void mma16816(float d[4], const uint32_t a[4], uint32_t b0, uint32_t b1) {
    asm volatile("mma.sync.aligned.m16n8k16.row.col.f32.bf16.bf16.f32 "
                 "{%0,%1,%2,%3}, {%4,%5,%6,%7}, {%8,%9}, {%0,%1,%2,%3};"
                 : "+f"(d[0]), "+f"(d[1]), "+f"(d[2]), "+f"(d[3])
                 : "r"(a[0]), "r"(a[1]), "r"(a[2]), "r"(a[3]), "r"(b0), "r"(b1));
}

// 4x2 layout k-chunk for k_z_mma: 32 rows x 64 cols per warp
__device__ __forceinline__ void mma_kchunk(uint32_t aH, uint32_t aL, uint32_t bH, uint32_t bL,
                                           uint32_t aro0, const uint32_t* bro,
                                           uint32_t lhi, uint32_t xorv, float acc[2][8][4]) {
#pragma unroll
    for (int ks = 0; ks < 4; ks++) {
        uint32_t cx = ((uint32_t)(ks * 32) + lhi) ^ xorv;
        uint32_t ah0[4], ah1[4], al0[4], al1[4];
        ldsm4(aH + aro0 + cx, ah0);
        ldsm4(aH + aro0 + 2048 + cx, ah1);
        ldsm4(aL + aro0 + cx, al0);
        ldsm4(aL + aro0 + 2048 + cx, al1);
#pragma unroll
        for (int g16 = 0; g16 < 4; g16++) {
            uint32_t bh[4], bl[4];
            ldsm4(bH + bro[g16] + cx, bh);
            ldsm4(bL + bro[g16] + cx, bl);
            const int g0 = 2 * g16, g1 = 2 * g16 + 1;
            mma16816(acc[0][g0], ah0, bh[0], bh[2]);
            mma16816(acc[1][g0], ah1, bh[0], bh[2]);
            mma16816(acc[0][g1], ah0, bh[1], bh[3]);
            mma16816(acc[1][g1], ah1, bh[1], bh[3]);
            mma16816(acc[0][g0], ah0, bl[0], bl[2]);
            mma16816(acc[1][g0], ah1, bl[0], bl[2]);
            mma16816(acc[0][g1], ah0, bl[1], bl[3]);
            mma16816(acc[1][g1], ah1, bl[1], bl[3]);
            mma16816(acc[0][g0], al0, bh[0], bh[2]);
            mma16816(acc[1][g0], al1, bh[0], bh[2]);
            mma16816(acc[0][g1], al0, bh[1], bh[3]);
            mma16816(acc[1][g1], al1, bh[1], bh[3]);
        }
    }
}

// attn k-chunk: 16 rows x 64 cols per warp, 32-col B chunk (2 ks steps).
// A in SW128 chunks (ksbase selects 32-col half), B in SW64 chunk.
__device__ __forceinline__ void mma_kchunk32(uint32_t aH, uint32_t aL, int ksbase,
                                             uint32_t bH, uint32_t bL,
                                             uint32_t aro0, const uint32_t* bro,
                                             uint32_t lhi, uint32_t xorv128, uint32_t xorv64,
                                             float acc[8][4]) {
#pragma unroll
    for (int ks = 0; ks < 2; ks++) {
        uint32_t cxa = ((uint32_t)((ksbase + ks) * 32) + lhi) ^ xorv128;
        uint32_t cxb = ((uint32_t)(ks * 32) + lhi) ^ xorv64;
        uint32_t ah[4], al[4];
        ldsm4(aH + aro0 + cxa, ah);
        ldsm4(aL + aro0 + cxa, al);
#pragma unroll
        for (int g16 = 0; g16 < 4; g16++) {
            uint32_t bh[4], bl[4];
            ldsm4(bH + bro[g16] + cxb, bh);
            ldsm4(bL + bro[g16] + cxb, bl);
            const int g0 = 2 * g16, g1 = 2 * g16 + 1;
            mma16816(acc[g0], ah, bh[0], bh[2]);
            mma16816(acc[g1], ah, bh[1], bh[3]);
            mma16816(acc[g0], ah, bl[0], bl[2]);
            mma16816(acc[g1], ah, bl[1], bl[3]);
            mma16816(acc[g0], al, bh[0], bh[2]);
            mma16816(acc[g1], al, bh[1], bh[3]);
        }
    }
}

// ---------------------------------------------------------------------------
// k_gt: G[c][e] = sum_d Wq[d][c]*Wk[d][e], bf16 hi/lo. grid 128, block 256.
// ---------------------------------------------------------------------------
__global__ void k_gt(const float* __restrict__ Wq, const float* __restrict__ Wk) {
    __shared__ float sq[2][CC];
    const int c0 = blockIdx.x * 2, e = threadIdx.x;
    sq[0][e] = Wq[e * CC + c0];
    sq[1][e] = Wq[e * CC + c0 + 1];
    __syncthreads();
    float a0 = 0.f, a1 = 0.f;
#pragma unroll 8
    for (int d = 0; d < CC; d++) {
        float wk = Wk[d * CC + e];
        a0 += sq[0][d] * wk;
        a1 += sq[1][d] * wk;
    }
    __nv_bfloat16 h0 = __float2bfloat16(a0), h1 = __float2bfloat16(a1);
    g_Gk_hi[c0 * CC + e] = h0;
    g_Gk_lo[c0 * CC + e] = __float2bfloat16(a0 - __bfloat162float(h0));
    g_Gk_hi[(c0 + 1) * CC + e] = h1;
    g_Gk_lo[(c0 + 1) * CC + e] = __float2bfloat16(a1 - __bfloat162float(h1));
}

// ---------------------------------------------------------------------------
// k_prep: Ft[b][n][c] = feat[b][c][n], bf16 hi/lo. grid (128,8,8), block (32,8)
// ---------------------------------------------------------------------------
__global__ void k_prep(const float* __restrict__ feat) {
    __shared__ float t[32][33];
    const int b = blockIdx.z, c0 = blockIdx.y * 32, n0 = blockIdx.x * 32;
    const int tx = threadIdx.x, ty = threadIdx.y;
    const float* F = feat + ((size_t)b * CC + c0) * NN + n0;
#pragma unroll
    for (int i = 0; i < 4; i++) t[ty + i * 8][tx] = F[(ty + i * 8) * NN + tx];
    __syncthreads();
#pragma unroll
    for (int i = 0; i < 4; i++) {
        int nr = ty + i * 8;
        float x = t[tx][nr];
        size_t o = ((size_t)b * NN + n0 + nr) * CC + c0 + tx;
        __nv_bfloat16 h = __float2bfloat16(x);
        g_Ft_hi[o] = h;
        g_Ft_lo[o] = __float2bfloat16(x - __bfloat162float(h));
    }
}

// ---------------------------------------------------------------------------
// k_z_mma: Zt[b][m][c] = sum_e Ft[m][e] * G[c][e].  grid (32, 8), 256 thr.
// ---------------------------------------------------------------------------
__global__ void __launch_bounds__(256, 1) k_z_mma() {
    extern __shared__ char sm[];
    const uint32_t smb = smem_u32(sm);
    const int tid = threadIdx.x, wid = tid >> 5, lane = tid & 31;
    const int m0 = blockIdx.x * 128, b = blockIdx.y;
    const int wr = wid & 3, wc = wid >> 2;
    const int l15 = lane & 15;
    const uint32_t lhi = (uint32_t)((lane >> 4) * 16);
    const uint32_t xorv = (uint32_t)((lane & 7) * 16);
    const uint32_t aro0 = (uint32_t)((wr * 32 + l15) * 128);
    uint32_t bro[4];
#pragma unroll
    for (int g16 = 0; g16 < 4; g16++) bro[g16] = (uint32_t)((wc * 64 + g16 * 16 + l15) * 128);

    cpa_chunk(smb + OFF_B, g_Gk_hi, tid);
    cpa_chunk(smb + OFF_B + CH, g_Gk_lo, tid);
    CPA_COMMIT();

    const __nv_bfloat16* Fh = g_Ft_hi + ((size_t)b * NN + m0) * CC;
    const __nv_bfloat16* Fl = g_Ft_lo + ((size_t)b * NN + m0) * CC;
#pragma unroll
    for (int cb = 0; cb < 8; cb++) {
        int p = cb >> 2, kc = cb & 3;
        copy_chunk(sm, OFF_A + cb * CH, (p ? Fl : Fh) + kc * 64, tid);
    }
    __syncthreads();

    for (int ch = 0; ch < 2; ch++) {
        float acc[2][8][4];
#pragma unroll
        for (int a = 0; a < 2; a++)
#pragma unroll
            for (int g = 0; g < 8; g++)
#pragma unroll
                for (int q = 0; q < 4; q++) acc[a][g][q] = 0.f;

#pragma unroll 1
        for (int kc = 0; kc < 4; kc++) {
            const int t = ch * 4 + kc;
            CPA_WAIT0();
            __syncthreads();
            if (t + 1 < 8) {
                int ch2 = (t + 1) >> 2, kc2 = (t + 1) & 3;
                uint32_t d = smb + OFF_B + ((t + 1) & 1) * BUFSZ;
                cpa_chunk(d, g_Gk_hi + (ch2 * 128) * CC + kc2 * 64, tid);
                cpa_chunk(d + CH, g_Gk_lo + (ch2 * 128) * CC + kc2 * 64, tid);
            }
            CPA_COMMIT();
            uint32_t bq = smb + OFF_B + (t & 1) * BUFSZ;
            mma_kchunk(smb + OFF_A + kc * CH, smb + OFF_A + (4 + kc) * CH,
                       bq, bq + CH, aro0, bro, lhi, xorv, acc);
        }

        const int g8 = lane >> 2, tig = lane & 3;
#pragma unroll
        for (int a = 0; a < 2; a++)
#pragma unroll
            for (int h = 0; h < 2; h++) {
                const int r = wr * 32 + a * 16 + h * 8 + g8;
                size_t rowoff = ((size_t)b * NN + m0 + r) * CC + ch * 128;
#pragma unroll
                for (int g = 0; g < 8; g++) {
                    const int cl = wc * 64 + g * 8 + tig * 2;
                    float x0 = acc[a][g][h * 2], x1 = acc[a][g][h * 2 + 1];
                    __nv_bfloat16 h0 = __float2bfloat16(x0), h1 = __float2bfloat16(x1);
                    __nv_bfloat16 l0 = __float2bfloat16(x0 - __bfloat162float(h0));
                    __nv_bfloat16 l1 = __float2bfloat16(x1 - __bfloat162float(h1));
                    *(__nv_bfloat162*)(g_Zt_hi + rowoff + cl) = __nv_bfloat162(h0, h1);
                    *(__nv_bfloat162*)(g_Zt_lo + rowoff + cl) = __nv_bfloat162(l0, l1);
                }
            }
    }
}

// ---------------------------------------------------------------------------
// k_attn_mma: streaming S = Ft·Zt^T. 64-row tiles, 256 thr, ~99.8 KB SMEM ->
// 2 independent CTAs per SM (barrier/epilogue bubbles of one CTA covered by
// the other). 4x2 warp layout (16 rows x 64 cols), B in 32-col SW64 chunks.
// grid (64, 8), 256 thr.
// ---------------------------------------------------------------------------
__global__ void __launch_bounds__(256, 2) k_attn_mma(const float* __restrict__ feat,
                                                     float* __restrict__ out) {
    extern __shared__ char sm[];
    const uint32_t smb = smem_u32(sm);
    const int tid = threadIdx.x, wid = tid >> 5, lane = tid & 31;
    const int n0 = blockIdx.x * 64, b = blockIdx.y;
    const int wr = wid & 3, wc = wid >> 2;
    const int l15 = lane & 15, g8 = lane >> 2, tig = lane & 3;
    const uint32_t lhi = (uint32_t)((lane >> 4) * 16);
    const uint32_t xorv128 = (uint32_t)((lane & 7) * 16);
    const uint32_t xorv64  = (uint32_t)(((l15 >> 1) & 3) * 16);
    const uint32_t aro0 = (uint32_t)((wr * 16 + l15) * 128);
    uint32_t bro[4];
#pragma unroll
    for (int g16 = 0; g16 < 4; g16++) bro[g16] = (uint32_t)((wc * 64 + g16 * 16 + l15) * 64);

    float* dlog = (float*)(sm + AE_DLOG);
    float* mmH  = (float*)(sm + AE_MM);    // [2][64]
    float* llH  = (float*)(sm + AE_LL);    // [2][64]
    float* diag = (float*)(sm + AE_DIAG);

    const __nv_bfloat16* Zh = g_Zt_hi + (size_t)b * NN * CC;
    const __nv_bfloat16* Zl = g_Zt_lo + (size_t)b * NN * CC;

    // kick off B chunk t=0 (mt=0, kc=0)
    cpa_chunk32(smb + AT_B, Zh, tid);
    cpa_chunk32(smb + AT_B + 8192, Zl, tid);
    CPA_COMMIT();

    // resident A: Ft rows n0..n0+63, hi/lo, 64-col SW128 chunks
    const __nv_bfloat16* Fh = g_Ft_hi + ((size_t)b * NN + n0) * CC;
    const __nv_bfloat16* Fl = g_Ft_lo + ((size_t)b * NN + n0) * CC;
#pragma unroll
    for (int cb = 0; cb < 8; cb++) {
        int p = cb >> 2, kc = cb & 3;
        copy_chunkA64(sm, AT_A + cb * ACH, (p ? Fl : Fh) + kc * 64, tid);
    }
    __syncthreads();

    // warp-private online softmax: 2 rows per lane (h=0: wr*16+g8, h=1: +8)
    float runm[2] = {-CUDART_INF_F, -CUDART_INF_F};
    float runl[2] = {0.f, 0.f};
    const int dtile = blockIdx.x >> 1;
    const int dbase = (blockIdx.x & 1) * 64;

#pragma unroll 1
    for (int mt = 0; mt < 32; mt++) {
        float acc[8][4];
#pragma unroll
        for (int g = 0; g < 8; g++)
#pragma unroll
            for (int q = 0; q < 4; q++) acc[g][q] = 0.f;

#pragma unroll 1
        for (int kc = 0; kc < 8; kc++) {
            const int t = mt * 8 + kc;
            CPA_WAIT0();
            __syncthreads();
            if (t + 1 < 256) {
                int mt2 = (t + 1) >> 3, kc2 = (t + 1) & 7;
                uint32_t d = smb + AT_B + ((t + 1) & 1) * BSTG;
                cpa_chunk32(d, Zh + (size_t)(mt2 * 128) * CC + kc2 * 32, tid);
                cpa_chunk32(d + 8192, Zl + (size_t)(mt2 * 128) * CC + kc2 * 32, tid);
            }
            CPA_COMMIT();
            uint32_t bq = smb + AT_B + (t & 1) * BSTG;
            const int ca = kc >> 1, ksbase = (kc & 1) * 2;
            mma_kchunk32(smb + AT_A + ca * ACH, smb + AT_A + (4 + ca) * ACH, ksbase,
                         bq, bq + 8192, aro0, bro, lhi, xorv128, xorv64, acc);
        }

        // ---- warp-private partial softmax over the 64-col slice ----
#pragma unroll
        for (int h = 0; h < 2; h++) {
            float mx = -CUDART_INF_F;
#pragma unroll
            for (int g = 0; g < 8; g++)
                mx = fmaxf(mx, fmaxf(acc[g][h * 2], acc[g][h * 2 + 1]));
            mx = fmaxf(mx, __shfl_xor_sync(0xffffffffu, mx, 1));
            mx = fmaxf(mx, __shfl_xor_sync(0xffffffffu, mx, 2));
            const float nm = fmaxf(runm[h], mx);
            float s = 0.f;
#pragma unroll
            for (int g = 0; g < 8; g++) {
                s += __expf(acc[g][h * 2] - nm);
                s += __expf(acc[g][h * 2 + 1] - nm);
            }
            s += __shfl_xor_sync(0xffffffffu, s, 1);
            s += __shfl_xor_sync(0xffffffffu, s, 2);
            runl[h] = runl[h] * __expf(runm[h] - nm) + s;
            runm[h] = nm;
        }

        if (mt == dtile) {  // diagonal tile: capture raw logit l_nn
#pragma unroll
            for (int h = 0; h < 2; h++) {
                const int rl = wr * 16 + h * 8 + g8;     // 0..63
#pragma unroll
                for (int g = 0; g < 8; g++)
#pragma unroll
                    for (int j = 0; j < 2; j++) {
                        const int cl = wc * 64 + g * 8 + tig * 2 + j;   // 0..127
                        if (cl == dbase + rl) dlog[rl] = acc[g][h * 2 + j];
                    }
            }
        }
    }

    // ---- one-time merge of the two half-row partials ----
    if (tig == 0) {
#pragma unroll
        for (int h = 0; h < 2; h++) {
            const int rl = wr * 16 + h * 8 + g8;
            mmH[wc * 64 + rl] = runm[h];
            llH[wc * 64 + rl] = runl[h];
        }
    }
    __syncthreads();
    if (tid < 64) {
        float m0 = mmH[tid], m1 = mmH[64 + tid];
        float m = fmaxf(m0, m1);
        float l = llH[tid] * __expf(m0 - m) + llH[64 + tid] * __expf(m1 - m);
        diag[tid] = __expf(dlog[tid] - m) / l;
    }
    __syncthreads();

    const float* F = feat + (size_t)b * CC * NN;
    float* O = out + (size_t)b * CC * NN;
    for (int u = tid; u < CC * 16; u += 256) {
        int c = u >> 4, seg = u & 15;
        float4 f = *(const float4*)(F + (size_t)c * NN + n0 + seg * 4);
        float4 o;
        o.x = f.x * diag[seg * 4 + 0];
        o.y = f.y * diag[seg * 4 + 1];
        o.z = f.z * diag[seg * 4 + 2];
        o.w = f.w * diag[seg * 4 + 3];
        *(float4*)(O + (size_t)c * NN + n0 + seg * 4) = o;
    }
}

// ---------------------------------------------------------------------------
extern "C" void kernel_launch(void* const* d_in, const int* in_sizes, int n_in,
                              void* d_out, int out_size) {
    const float* feat = (const float*)d_in[0];  // [B,C,N]
    const float* Wq   = (const float*)d_in[1];  // [C,C]
    const float* Wk   = (const float*)d_in[2];  // [C,C]
    float* out = (float*)d_out;                 // [B,C,N]

    cudaFuncSetAttribute(k_z_mma, cudaFuncAttributeMaxDynamicSharedMemorySize, SMEM_Z);
    cudaFuncSetAttribute(k_attn_mma, cudaFuncAttributeMaxDynamicSharedMemorySize, SMEM_AT);

    k_gt<<<CC / 2, CC>>>(Wq, Wk);
    k_prep<<<dim3(NN / 32, CC / 32, BB), dim3(32, 8)>>>(feat);
    k_z_mma<<<dim3(NN / 128, BB), 256, SMEM_Z>>>();
    k_attn_mma<<<dim3(NN / 64, BB), 256, SMEM_AT>>>(feat, out);
}

// round 17
// speedup vs baseline: 1.0572x; 1.0572x over previous
#include <cuda_runtime.h>
#include <cuda_bf16.h>
#include <cstdint>
#include <math_constants.h>

#define BB 8
#define CC 256
#define NN 4096

// ---------------- device scratch (allocation-free rule) ----------------
__device__ __nv_bfloat16 g_Ft_hi[BB * NN * CC];   // feat^T [b][n][c]
__device__ __nv_bfloat16 g_Ft_lo[BB * NN * CC];
__device__ __nv_bfloat16 g_Zt_hi[BB * NN * CC];   // Z^T [b][m][c]
__device__ __nv_bfloat16 g_Zt_lo[BB * NN * CC];
__device__ __nv_bfloat16 g_Gk_hi[CC * CC];        // G [c][e]
__device__ __nv_bfloat16 g_Gk_lo[CC * CC];

// ---------------- SMEM layout ----------------
#define CH       16384                 // one 128x64 bf16 chunk, SW128 swizzled
#define OFF_A    0                     // 8 chunks (hi:0..3, lo:4..7) = 131072
#define OFF_B    131072                // 2 bufs x (hi+lo) = 2*32768
#define BUFSZ    32768
#define OFF_EPI  196608
#define EP_DLOG  (OFF_EPI + 0)         // 512 B
#define EP_MM    (OFF_EPI + 512)       // 2*512 B  (per-half row max)
#define EP_LL    (OFF_EPI + 1536)      // 2*512 B  (per-half row sumexp)
#define EP_DIAG  (OFF_EPI + 2560)      // 512 B
#define SMEM_TOTAL 199680

__device__ __forceinline__ uint32_t smem_u32(const void* p) {
    uint32_t a;
    asm("{ .reg .u64 t; cvta.to.shared.u64 t, %1; cvt.u32.u64 %0, t; }" : "=r"(a) : "l"(p));
    return a;
}

#define CPA_COMMIT() asm volatile("cp.async.commit_group;" ::: "memory")
#define CPA_WAIT0()  asm volatile("cp.async.wait_group 0;" ::: "memory")

// 128 rows x 64 bf16 chunk (gmem row stride CC) -> SW128 swizzled smem, cp.async
__device__ __forceinline__ void cpa_chunk(uint32_t dst, const __nv_bfloat16* g, int tid) {
#pragma unroll
    for (int it = 0; it < 4; it++) {
        int u = tid + it * 256;
        int row = u >> 3, seg = u & 7;
        uint32_t bo = (uint32_t)(row * 128 + seg * 16);
        bo ^= ((bo >> 3) & 0x70);
        asm volatile("cp.async.cg.shared.global [%0], [%1], 16;"
                     :: "r"(dst + bo), "l"((const void*)(g + row * CC + seg * 8)) : "memory");
    }
}
__device__ __forceinline__ void cpa_chunk512(uint32_t dst, const __nv_bfloat16* g, int tid) {
#pragma unroll
    for (int it = 0; it < 2; it++) {
        int u = tid + it * 512;
        int row = u >> 3, seg = u & 7;
        uint32_t bo = (uint32_t)(row * 128 + seg * 16);
        bo ^= ((bo >> 3) & 0x70);
        asm volatile("cp.async.cg.shared.global [%0], [%1], 16;"
                     :: "r"(dst + bo), "l"((const void*)(g + row * CC + seg * 8)) : "memory");
    }
}

__device__ __forceinline__ void copy_chunk(char* sm, uint32_t dst, const __nv_bfloat16* g, int tid) {
#pragma unroll
    for (int it = 0; it < 4; it++) {
        int u = tid + it * 256;
        int row = u >> 3, seg = u & 7;
        uint4 v = *(const uint4*)(g + row * CC + seg * 8);
        uint32_t bo = (uint32_t)(row * 128 + seg * 16);
        bo ^= ((bo >> 3) & 0x70);
        *(uint4*)(sm + dst + bo) = v;
    }
}
__device__ __forceinline__ void copy_chunk512(char* sm, uint32_t dst, const __nv_bfloat16* g, int tid) {
#pragma unroll
    for (int it = 0; it < 2; it++) {
        int u = tid + it * 512;
        int row = u >> 3, seg = u & 7;
        uint4 v = *(const uint4*)(g + row * CC + seg * 8);
        uint32_t bo = (uint32_t)(row * 128 + seg * 16);
        bo ^= ((bo >> 3) & 0x70);
        *(uint4*)(sm + dst + bo) = v;
    }
}

__device__ __forceinline__ void ldsm4(uint32_t addr, uint32_t r[4]) {
    asm volatile("ldmatrix.sync.aligned.m8n8.x4.shared.b16 {%0,%1,%2,%3}, [%4];"
                 : "=r"(r[0]), "=r"(r[1]), "=r"(r[2]), "=r"(r[3]) : "r"(addr));
}

__device__ __forceinline__ void mma16816(float d[4], const uint32_t a[4], uint32_t b0, uint32_t b1) {
    asm volatile("mma.sync.aligned.m16n8k16.row.col.f32.bf16.bf16.f32 "
                 "{%0,%1,%2,%3}, {%4,%5,%6,%7}, {%8,%9}, {%0,%1,%2,%3};"
                 : "+f"(d[0]), "+f"(d[1]), "+f"(d[2]), "+f"(d[3])
                 : "r"(a[0]), "r"(a[1]), "r"(a[2]), "r"(a[3]), "r"(b0), "r"(b1));
}

// 4x2 warp layout k-chunk: 32 rows x 64 cols per warp (k_z_mma, 8 warps)
__device__ __forceinline__ void mma_kchunk(uint32_t aH, uint32_t aL, uint32_t bH, uint32_t bL,
                                           uint32_t aro0, const uint32_t* bro,
                                           uint32_t lhi, uint32_t xorv, float acc[2][8][4]) {
#pragma unroll
    for (int ks = 0; ks < 4; ks++) {
        uint32_t cx = ((uint32_t)(ks * 32) + lhi) ^ xorv;
        uint32_t ah0[4], ah1[4], al0[4], al1[4];
        ldsm4(aH + aro0 + cx, ah0);
        ldsm4(aH + aro0 + 2048 + cx, ah1);
        ldsm4(aL + aro0 + cx, al0);
        ldsm4(aL + aro0 + 2048 + cx, al1);
#pragma unroll
        for (int g16 = 0; g16 < 4; g16++) {
            uint32_t bh[4], bl[4];
            ldsm4(bH + bro[g16] + cx, bh);
            ldsm4(bL + bro[g16] + cx, bl);
            const int g0 = 2 * g16, g1 = 2 * g16 + 1;
            mma16816(acc[0][g0], ah0, bh[0], bh[2]);
            mma16816(acc[1][g0], ah1, bh[0], bh[2]);
            mma16816(acc[0][g1], ah0, bh[1], bh[3]);
            mma16816(acc[1][g1], ah1, bh[1], bh[3]);
            mma16816(acc[0][g0], ah0, bl[0], bl[2]);
            mma16816(acc[1][g0], ah1, bl[0], bl[2]);
            mma16816(acc[0][g1], ah0, bl[1], bl[3]);
            mma16816(acc[1][g1], ah1, bl[1], bl[3]);
            mma16816(acc[0][g0], al0, bh[0], bh[2]);
            mma16816(acc[1][g0], al1, bh[0], bh[2]);
            mma16816(acc[0][g1], al0, bh[1], bh[3]);
            mma16816(acc[1][g1], al1, bh[1], bh[3]);
        }
    }
}

// 8x2 warp layout k-chunk, RAW-distance-4 ordering: B loaded for PAIRS of
// g16 groups, mma issued pass-ordered so same-acc reuse distance = 4.
__device__ __forceinline__ void mma_kchunk_82(uint32_t aH, uint32_t aL, uint32_t bH, uint32_t bL,
                                              uint32_t aro0, const uint32_t* bro,
                                              uint32_t lhi, uint32_t xorv, float acc[8][4]) {
#pragma unroll
    for (int ks = 0; ks < 4; ks++) {
        uint32_t cx = ((uint32_t)(ks * 32) + lhi) ^ xorv;
        uint32_t ah[4], al[4];
        ldsm4(aH + aro0 + cx, ah);
        ldsm4(aL + aro0 + cx, al);
#pragma unroll
        for (int gp = 0; gp < 2; gp++) {
            uint32_t bh0[4], bl0[4], bh1[4], bl1[4];
            ldsm4(bH + bro[2 * gp] + cx, bh0);
            ldsm4(bL + bro[2 * gp] + cx, bl0);
            ldsm4(bH + bro[2 * gp + 1] + cx, bh1);
            ldsm4(bL + bro[2 * gp + 1] + cx, bl1);
            const int g0 = 4 * gp, g1 = 4 * gp + 1, g2 = 4 * gp + 2, g3 = 4 * gp + 3;
            // pass 1: ah*bh (4 distinct accs)
            mma16816(acc[g0], ah, bh0[0], bh0[2]);
            mma16816(acc[g1], ah, bh0[1], bh0[3]);
            mma16816(acc[g2], ah, bh1[0], bh1[2]);
            mma16816(acc[g3], ah, bh1[1], bh1[3]);
            // pass 2: ah*bl
            mma16816(acc[g0], ah, bl0[0], bl0[2]);
            mma16816(acc[g1], ah, bl0[1], bl0[3]);
            mma16816(acc[g2], ah, bl1[0], bl1[2]);
            mma16816(acc[g3], ah, bl1[1], bl1[3]);
            // pass 3: al*bh
            mma16816(acc[g0], al, bh0[0], bh0[2]);
            mma16816(acc[g1], al, bh0[1], bh0[3]);
            mma16816(acc[g2], al, bh1[0], bh1[2]);
            mma16816(acc[g3], al, bh1[1], bh1[3]);
        }
    }
}

// ---------------------------------------------------------------------------
// k_gt: G[c][e] = sum_d Wq[d][c]*Wk[d][e], bf16 hi/lo.
// 16 blocks x 256 thr; block computes 16 c's x 256 e; Wq slice staged in smem.
// ---------------------------------------------------------------------------
__global__ void k_gt(const float* __restrict__ Wq, const float* __restrict__ Wk) {
    __shared__ float sq[CC][16];
    const int c0 = blockIdx.x * 16, e = threadIdx.x;
    for (int u = threadIdx.x; u < CC * 16; u += 256) {
        int d = u >> 4, j = u & 15;
        sq[d][j] = Wq[d * CC + c0 + j];
    }
    __syncthreads();
    float acc[16];
#pragma unroll
    for (int j = 0; j < 16; j++) acc[j] = 0.f;
#pragma unroll 4
    for (int d = 0; d < CC; d++) {
        float wk = Wk[d * CC + e];
#pragma unroll
        for (int j = 0; j < 16; j++) acc[j] += sq[d][j] * wk;
    }
#pragma unroll
    for (int j = 0; j < 16; j++) {
        float a = acc[j];
        __nv_bfloat16 h = __float2bfloat16(a);
        g_Gk_hi[(c0 + j) * CC + e] = h;
        g_Gk_lo[(c0 + j) * CC + e] = __float2bfloat16(a - __bfloat162float(h));
    }
}

// ---------------------------------------------------------------------------
// k_prep: Ft[b][n][c] = feat[b][c][n], bf16 hi/lo. grid (128,8,8), block (32,8)
// ---------------------------------------------------------------------------
__global__ void k_prep(const float* __restrict__ feat) {
    __shared__ float t[32][33];
    const int b = blockIdx.z, c0 = blockIdx.y * 32, n0 = blockIdx.x * 32;
    const int tx = threadIdx.x, ty = threadIdx.y;
    const float* F = feat + ((size_t)b * CC + c0) * NN + n0;
#pragma unroll
    for (int i = 0; i < 4; i++) t[ty + i * 8][tx] = F[(ty + i * 8) * NN + tx];
    __syncthreads();
#pragma unroll
    for (int i = 0; i < 4; i++) {
        int nr = ty + i * 8;
        float x = t[tx][nr];
        size_t o = ((size_t)b * NN + n0 + nr) * CC + c0 + tx;
        __nv_bfloat16 h = __float2bfloat16(x);
        g_Ft_hi[o] = h;
        g_Ft_lo[o] = __float2bfloat16(x - __bfloat162float(h));
    }
}

// ---------------------------------------------------------------------------
// k_z_mma: Zt[b][m][c] = sum_e Ft[m][e] * G[c][e].  grid (32, 8), 256 thr.
// ---------------------------------------------------------------------------
__global__ void __launch_bounds__(256, 1) k_z_mma() {
    extern __shared__ char sm[];
    const uint32_t smb = smem_u32(sm);
    const int tid = threadIdx.x, wid = tid >> 5, lane = tid & 31;
    const int m0 = blockIdx.x * 128, b = blockIdx.y;
    const int wr = wid & 3, wc = wid >> 2;
    const int l15 = lane & 15;
    const uint32_t lhi = (uint32_t)((lane >> 4) * 16);
    const uint32_t xorv = (uint32_t)((lane & 7) * 16);
    const uint32_t aro0 = (uint32_t)((wr * 32 + l15) * 128);
    uint32_t bro[4];
#pragma unroll
    for (int g16 = 0; g16 < 4; g16++) bro[g16] = (uint32_t)((wc * 64 + g16 * 16 + l15) * 128);

    cpa_chunk(smb + OFF_B, g_Gk_hi, tid);
    cpa_chunk(smb + OFF_B + CH, g_Gk_lo, tid);
    CPA_COMMIT();

    const __nv_bfloat16* Fh = g_Ft_hi + ((size_t)b * NN + m0) * CC;
    const __nv_bfloat16* Fl = g_Ft_lo + ((size_t)b * NN + m0) * CC;
#pragma unroll
    for (int cb = 0; cb < 8; cb++) {
        int p = cb >> 2, kc = cb & 3;
        copy_chunk(sm, OFF_A + cb * CH, (p ? Fl : Fh) + kc * 64, tid);
    }
    __syncthreads();

    for (int ch = 0; ch < 2; ch++) {
        float acc[2][8][4];
#pragma unroll
        for (int a = 0; a < 2; a++)
#pragma unroll
            for (int g = 0; g < 8; g++)
#pragma unroll
                for (int q = 0; q < 4; q++) acc[a][g][q] = 0.f;

#pragma unroll 1
        for (int kc = 0; kc < 4; kc++) {
            const int t = ch * 4 + kc;
            CPA_WAIT0();
            __syncthreads();
            if (t + 1 < 8) {
                int ch2 = (t + 1) >> 2, kc2 = (t + 1) & 3;
                uint32_t d = smb + OFF_B + ((t + 1) & 1) * BUFSZ;
                cpa_chunk(d, g_Gk_hi + (ch2 * 128) * CC + kc2 * 64, tid);
                cpa_chunk(d + CH, g_Gk_lo + (ch2 * 128) * CC + kc2 * 64, tid);
            }
            CPA_COMMIT();
            uint32_t bq = smb + OFF_B + (t & 1) * BUFSZ;
            mma_kchunk(smb + OFF_A + kc * CH, smb + OFF_A + (4 + kc) * CH,
                       bq, bq + CH, aro0, bro, lhi, xorv, acc);
        }

        const int g8 = lane >> 2, tig = lane & 3;
#pragma unroll
        for (int a = 0; a < 2; a++)
#pragma unroll
            for (int h = 0; h < 2; h++) {
                const int r = wr * 32 + a * 16 + h * 8 + g8;
                size_t rowoff = ((size_t)b * NN + m0 + r) * CC + ch * 128;
#pragma unroll
                for (int g = 0; g < 8; g++) {
                    const int cl = wc * 64 + g * 8 + tig * 2;
                    float x0 = acc[a][g][h * 2], x1 = acc[a][g][h * 2 + 1];
                    __nv_bfloat16 h0 = __float2bfloat16(x0), h1 = __float2bfloat16(x1);
                    __nv_bfloat16 l0 = __float2bfloat16(x0 - __bfloat162float(h0));
                    __nv_bfloat16 l1 = __float2bfloat16(x1 - __bfloat162float(h1));
                    *(__nv_bfloat162*)(g_Zt_hi + rowoff + cl) = __nv_bfloat162(h0, h1);
                    *(__nv_bfloat162*)(g_Zt_lo + rowoff + cl) = __nv_bfloat162(l0, l1);
                }
            }
    }
}

// ---------------------------------------------------------------------------
// k_attn_mma: streaming S = Ft·Zt^T. 512 threads, 8x2 warp layout (16 rows x
// 64 cols per warp), RAW-distance-4 mma ordering. Warp-private partial
// softmax; two-partial merge at end.  grid (32, 8), 512 thr.
// ---------------------------------------------------------------------------
__global__ void __launch_bounds__(512, 1) k_attn_mma(const float* __restrict__ feat,
                                                     float* __restrict__ out) {
    extern __shared__ char sm[];
    const uint32_t smb = smem_u32(sm);
    const int tid = threadIdx.x, wid = tid >> 5, lane = tid & 31;
    const int n0 = blockIdx.x * 128, b = blockIdx.y;
    const int wr = wid & 7, wc = wid >> 3;
    const int l15 = lane & 15, g8 = lane >> 2, tig = lane & 3;
    const uint32_t lhi = (uint32_t)((lane >> 4) * 16);
    const uint32_t xorv = (uint32_t)((lane & 7) * 16);
    const uint32_t aro0 = (uint32_t)((wr * 16 + l15) * 128);
    uint32_t bro[4];
#pragma unroll
    for (int g16 = 0; g16 < 4; g16++) bro[g16] = (uint32_t)((wc * 64 + g16 * 16 + l15) * 128);

    float* dlog = (float*)(sm + EP_DLOG);
    float* mmH  = (float*)(sm + EP_MM);    // [2][128]
    float* llH  = (float*)(sm + EP_LL);    // [2][128]
    float* diag = (float*)(sm + EP_DIAG);

    const __nv_bfloat16* Zh = g_Zt_hi + (size_t)b * NN * CC;
    const __nv_bfloat16* Zl = g_Zt_lo + (size_t)b * NN * CC;

    cpa_chunk512(smb + OFF_B, Zh, tid);
    cpa_chunk512(smb + OFF_B + CH, Zl, tid);
    CPA_COMMIT();

    const __nv_bfloat16* Fh = g_Ft_hi + ((size_t)b * NN + n0) * CC;
    const __nv_bfloat16* Fl = g_Ft_lo + ((size_t)b * NN + n0) * CC;
#pragma unroll
    for (int cb = 0; cb < 8; cb++) {
        int p = cb >> 2, kc = cb & 3;
        copy_chunk512(sm, OFF_A + cb * CH, (p ? Fl : Fh) + kc * 64, tid);
    }
    __syncthreads();

    // warp-private online softmax state: 2 rows per lane
    float runm[2] = {-CUDART_INF_F, -CUDART_INF_F};
    float runl[2] = {0.f, 0.f};

#pragma unroll 1
    for (int mt = 0; mt < 32; mt++) {
        float acc[8][4];
#pragma unroll
        for (int g = 0; g < 8; g++)
#pragma unroll
            for (int q = 0; q < 4; q++) acc[g][q] = 0.f;

#pragma unroll 1
        for (int kc = 0; kc < 4; kc++) {
            const int t = mt * 4 + kc;
            CPA_WAIT0();
            __syncthreads();
            if (t + 1 < 128) {
                int mt2 = (t + 1) >> 2, kc2 = (t + 1) & 3;
                uint32_t d = smb + OFF_B + ((t + 1) & 1) * BUFSZ;
                cpa_chunk512(d, Zh + (size_t)(mt2 * 128) * CC + kc2 * 64, tid);
                cpa_chunk512(d + CH, Zl + (size_t)(mt2 * 128) * CC + kc2 * 64, tid);
            }
            CPA_COMMIT();
            uint32_t bq = smb + OFF_B + (t & 1) * BUFSZ;
            mma_kchunk_82(smb + OFF_A + kc * CH, smb + OFF_A + (4 + kc) * CH,
                          bq, bq + CH, aro0, bro, lhi, xorv, acc);
        }

        // ---- warp-private partial softmax over the 64-col slice ----
#pragma unroll
        for (int h = 0; h < 2; h++) {
            float mx = -CUDART_INF_F;
#pragma unroll
            for (int g = 0; g < 8; g++)
                mx = fmaxf(mx, fmaxf(acc[g][h * 2], acc[g][h * 2 + 1]));
            mx = fmaxf(mx, __shfl_xor_sync(0xffffffffu, mx, 1));
            mx = fmaxf(mx, __shfl_xor_sync(0xffffffffu, mx, 2));
            const float nm = fmaxf(runm[h], mx);
            float s = 0.f;
#pragma unroll
            for (int g = 0; g < 8; g++) {
                s += __expf(acc[g][h * 2] - nm);
                s += __expf(acc[g][h * 2 + 1] - nm);
            }
            s += __shfl_xor_sync(0xffffffffu, s, 1);
            s += __shfl_xor_sync(0xffffffffu, s, 2);
            runl[h] = runl[h] * __expf(runm[h] - nm) + s;
            runm[h] = nm;
        }

        if (mt == blockIdx.x) {  // diagonal tile: capture raw logit l_nn
#pragma unroll
            for (int h = 0; h < 2; h++) {
                const int rl = wr * 16 + h * 8 + g8;
#pragma unroll
                for (int g = 0; g < 8; g++)
#pragma unroll
                    for (int j = 0; j < 2; j++) {
                        const int cl = wc * 64 + g * 8 + tig * 2 + j;
                        if (cl == rl) dlog[rl] = acc[g][h * 2 + j];
                    }
            }
        }
    }

    // ---- one-time merge of the two half-row partials ----
    if (tig == 0) {
#pragma unroll
        for (int h = 0; h < 2; h++) {
            const int rl = wr * 16 + h * 8 + g8;
            mmH[wc * 128 + rl] = runm[h];
            llH[wc * 128 + rl] = runl[h];
        }
    }
    __syncthreads();
    if (tid < 128) {
        float m0 = mmH[tid], m1 = mmH[128 + tid];
        float m = fmaxf(m0, m1);
        float l = llH[tid] * __expf(m0 - m) + llH[128 + tid] * __expf(m1 - m);
        diag[tid] = __expf(dlog[tid] - m) / l;
    }
    __syncthreads();

    const float* F = feat + (size_t)b * CC * NN;
    float* O = out + (size_t)b * CC * NN;
    for (int u = tid; u < CC * 32; u += 512) {
        int c = u >> 5, seg = u & 31;
        float4 f = *(const float4*)(F + (size_t)c * NN + n0 + seg * 4);
        float4 o;
        o.x = f.x * diag[seg * 4 + 0];
        o.y = f.y * diag[seg * 4 + 1];
        o.z = f.z * diag[seg * 4 + 2];
        o.w = f.w * diag[seg * 4 + 3];
        *(float4*)(O + (size_t)c * NN + n0 + seg * 4) = o;
    }
}

// ---------------------------------------------------------------------------
extern "C" void kernel_launch(void* const* d_in, const int* in_sizes, int n_in,
                              void* d_out, int out_size) {
    const float* feat = (const float*)d_in[0];  // [B,C,N]
    const float* Wq   = (const float*)d_in[1];  // [C,C]
    const float* Wk   = (const float*)d_in[2];  // [C,C]
    float* out = (float*)d_out;                 // [B,C,N]

    cudaFuncSetAttribute(k_z_mma, cudaFuncAttributeMaxDynamicSharedMemorySize, SMEM_TOTAL);
    cudaFuncSetAttribute(k_attn_mma, cudaFuncAttributeMaxDynamicSharedMemorySize, SMEM_TOTAL);

    k_gt<<<CC / 16, CC>>>(Wq, Wk);
    k_prep<<<dim3(NN / 32, CC / 32, BB), dim3(32, 8)>>>(feat);
    k_z_mma<<<dim3(NN / 128, BB), 256, SMEM_TOTAL>>>();
    k_attn_mma<<<dim3(NN / 128, BB), 512, SMEM_TOTAL>>>(feat, out);
}